// round 1
// baseline (speedup 1.0000x reference)
#include <cuda_runtime.h>
#include <math.h>

// Problem constants
#define TOK 2048
#define HID 1024
#define NEXP 8
#define INTER 4096
#define SOFTCAP 30.0f

// ---------------------------------------------------------------------------
// Scratch (device globals -- no allocation allowed). Zero-initialized at load.
// ---------------------------------------------------------------------------
__device__ int   g_cnt[NEXP];
__device__ int   g_list[NEXP][TOK];
__device__ float g_wl[NEXP][TOK];
// act buffer: per expert up to TOK rows of INTER floats (268 MB, .bss)
__device__ float g_act[(size_t)NEXP * TOK * INTER];

// ---------------------------------------------------------------------------
// Zero the output + counts
// ---------------------------------------------------------------------------
__global__ void k_zero_out(float* __restrict__ out, int n) {
    int i = blockIdx.x * blockDim.x + threadIdx.x;
    if (i < n) out[i] = 0.0f;
}

__global__ void k_init() {
    if (threadIdx.x < NEXP) g_cnt[threadIdx.x] = 0;
}

// ---------------------------------------------------------------------------
// Router: logits = x @ wg^T ; softcap ; softmax-top2 ; renormalize ; scatter
// One block (128 threads) per token.
// ---------------------------------------------------------------------------
__global__ void k_router(const float* __restrict__ x, const float* __restrict__ wg) {
    const int t = blockIdx.x;
    const float* xr = x + (size_t)t * HID;

    float acc[NEXP];
#pragma unroll
    for (int e = 0; e < NEXP; e++) acc[e] = 0.0f;

    for (int h = threadIdx.x; h < HID; h += 128) {
        float xv = xr[h];
#pragma unroll
        for (int e = 0; e < NEXP; e++)
            acc[e] = fmaf(xv, wg[e * HID + h], acc[e]);
    }

    // warp reduce
#pragma unroll
    for (int o = 16; o > 0; o >>= 1) {
#pragma unroll
        for (int e = 0; e < NEXP; e++)
            acc[e] += __shfl_down_sync(0xffffffffu, acc[e], o);
    }

    __shared__ float red[4][NEXP];
    int wid = threadIdx.x >> 5;
    int lane = threadIdx.x & 31;
    if (lane == 0) {
#pragma unroll
        for (int e = 0; e < NEXP; e++) red[wid][e] = acc[e];
    }
    __syncthreads();

    if (threadIdx.x == 0) {
        float l[NEXP];
#pragma unroll
        for (int e = 0; e < NEXP; e++) {
            float v = red[0][e] + red[1][e] + red[2][e] + red[3][e];
            l[e] = SOFTCAP * tanhf(v * (1.0f / SOFTCAP));
        }
        // top-1 (ties -> lowest index, matches jax.lax.top_k)
        int i0 = 0;
#pragma unroll
        for (int e = 1; e < NEXP; e++)
            if (l[e] > l[i0]) i0 = e;
        // top-2
        int i1 = (i0 == 0) ? 1 : 0;
#pragma unroll
        for (int e = 0; e < NEXP; e++)
            if (e != i0 && l[e] > l[i1]) i1 = e;

        // renormalized weights; softmax denominator cancels
        float m = l[i0];  // l[i0] >= l[i1]
        float e0 = expf(l[i0] - m);
        float e1 = expf(l[i1] - m);
        float inv = 1.0f / (e0 + e1);

        int p0 = atomicAdd(&g_cnt[i0], 1);
        g_list[i0][p0] = t;
        g_wl[i0][p0] = e0 * inv;
        int p1 = atomicAdd(&g_cnt[i1], 1);
        g_list[i1][p1] = t;
        g_wl[i1][p1] = e1 * inv;
    }
}

// ---------------------------------------------------------------------------
// GEMM1: for expert e, gathered tokens M x HID  @  (w1,w3)[e] INTER x HID ^T
//   act = gelu_exact(h1) * h3, stored to g_act in list order.
// Tiles: BM=64, BN=64, BK=16, 256 threads, 4x4 micro-tile, dual-B (w1,w3).
// grid = (TOK/64 m-tiles [fast], INTER/64 n-tiles, NEXP)
// ---------------------------------------------------------------------------
__global__ void k_gemm1(const float* __restrict__ x,
                        const float* __restrict__ w1,
                        const float* __restrict__ w3) {
    const int e = blockIdx.z;
    const int cnt = g_cnt[e];
    const int m0 = blockIdx.x * 64;
    if (m0 >= cnt) return;
    const int n0 = blockIdx.y * 64;

    __shared__ float As[16][64];
    __shared__ float B1s[16][64];
    __shared__ float B3s[16][64];
    __shared__ int rows[64];

    const int tid = threadIdx.x;
    if (tid < 64) {
        int m = m0 + tid;
        rows[tid] = g_list[e][m < cnt ? m : (cnt - 1)];
    }
    __syncthreads();

    const int lr = tid >> 2;            // 0..63 (row within tile)
    const int lc = (tid & 3) * 4;       // 0,4,8,12 (k offset)
    const float* ap  = x  + (size_t)rows[lr] * HID + lc;
    const float* b1p = w1 + ((size_t)e * INTER + n0 + lr) * HID + lc;
    const float* b3p = w3 + ((size_t)e * INTER + n0 + lr) * HID + lc;

    const int tx = tid & 15;
    const int ty = tid >> 4;

    float acc1[4][4];
    float acc3[4][4];
#pragma unroll
    for (int i = 0; i < 4; i++)
#pragma unroll
        for (int j = 0; j < 4; j++) { acc1[i][j] = 0.0f; acc3[i][j] = 0.0f; }

    for (int k0 = 0; k0 < HID; k0 += 16) {
        float4 av  = *(const float4*)(ap + k0);
        float4 b1v = *(const float4*)(b1p + k0);
        float4 b3v = *(const float4*)(b3p + k0);
        As[lc + 0][lr] = av.x;  As[lc + 1][lr] = av.y;
        As[lc + 2][lr] = av.z;  As[lc + 3][lr] = av.w;
        B1s[lc + 0][lr] = b1v.x; B1s[lc + 1][lr] = b1v.y;
        B1s[lc + 2][lr] = b1v.z; B1s[lc + 3][lr] = b1v.w;
        B3s[lc + 0][lr] = b3v.x; B3s[lc + 1][lr] = b3v.y;
        B3s[lc + 2][lr] = b3v.z; B3s[lc + 3][lr] = b3v.w;
        __syncthreads();

#pragma unroll
        for (int kk = 0; kk < 16; kk++) {
            float4 a  = *(const float4*)&As[kk][ty * 4];
            float4 b1 = *(const float4*)&B1s[kk][tx * 4];
            float4 b3 = *(const float4*)&B3s[kk][tx * 4];
            float aa[4]  = {a.x, a.y, a.z, a.w};
            float bb1[4] = {b1.x, b1.y, b1.z, b1.w};
            float bb3[4] = {b3.x, b3.y, b3.z, b3.w};
#pragma unroll
            for (int i = 0; i < 4; i++) {
#pragma unroll
                for (int j = 0; j < 4; j++) {
                    acc1[i][j] = fmaf(aa[i], bb1[j], acc1[i][j]);
                    acc3[i][j] = fmaf(aa[i], bb3[j], acc3[i][j]);
                }
            }
        }
        __syncthreads();
    }

    // epilogue: exact gelu(h1) * h3 -> g_act
#pragma unroll
    for (int i = 0; i < 4; i++) {
        int m = m0 + ty * 4 + i;
        if (m < cnt) {
            float4 o;
            float* op = (float*)&o;
#pragma unroll
            for (int j = 0; j < 4; j++) {
                float h1 = acc1[i][j];
                float g = 0.5f * h1 * (1.0f + erff(h1 * 0.70710678118654752f));
                op[j] = g * acc3[i][j];
            }
            *(float4*)&g_act[((size_t)e * TOK + m) * INTER + n0 + tx * 4] = o;
        }
    }
}

// ---------------------------------------------------------------------------
// GEMM2: act (list-order rows) M x INTER  @  w2[e] HID x INTER ^T,
//   scaled by routing weight, atomically accumulated into out[token].
// grid = (TOK/64, HID/64, NEXP)
// ---------------------------------------------------------------------------
__global__ void k_gemm2(const float* __restrict__ w2, float* __restrict__ out) {
    const int e = blockIdx.z;
    const int cnt = g_cnt[e];
    const int m0 = blockIdx.x * 64;
    if (m0 >= cnt) return;
    const int n0 = blockIdx.y * 64;

    __shared__ float As[16][64];
    __shared__ float Bs[16][64];

    const int tid = threadIdx.x;
    const int lr = tid >> 2;
    const int lc = (tid & 3) * 4;
    // rows beyond cnt are in-bounds (<= TOK-1) and never stored, safe to read
    const float* ap = g_act + ((size_t)e * TOK + (m0 + lr)) * INTER + lc;
    const float* bp = w2 + ((size_t)e * HID + n0 + lr) * INTER + lc;

    const int tx = tid & 15;
    const int ty = tid >> 4;

    float acc[4][4];
#pragma unroll
    for (int i = 0; i < 4; i++)
#pragma unroll
        for (int j = 0; j < 4; j++) acc[i][j] = 0.0f;

    for (int k0 = 0; k0 < INTER; k0 += 16) {
        float4 av = *(const float4*)(ap + k0);
        float4 bv = *(const float4*)(bp + k0);
        As[lc + 0][lr] = av.x; As[lc + 1][lr] = av.y;
        As[lc + 2][lr] = av.z; As[lc + 3][lr] = av.w;
        Bs[lc + 0][lr] = bv.x; Bs[lc + 1][lr] = bv.y;
        Bs[lc + 2][lr] = bv.z; Bs[lc + 3][lr] = bv.w;
        __syncthreads();

#pragma unroll
        for (int kk = 0; kk < 16; kk++) {
            float4 a = *(const float4*)&As[kk][ty * 4];
            float4 b = *(const float4*)&Bs[kk][tx * 4];
            float aa[4] = {a.x, a.y, a.z, a.w};
            float bb[4] = {b.x, b.y, b.z, b.w};
#pragma unroll
            for (int i = 0; i < 4; i++)
#pragma unroll
                for (int j = 0; j < 4; j++)
                    acc[i][j] = fmaf(aa[i], bb[j], acc[i][j]);
        }
        __syncthreads();
    }

#pragma unroll
    for (int i = 0; i < 4; i++) {
        int m = m0 + ty * 4 + i;
        if (m < cnt) {
            int t = g_list[e][m];
            float w = g_wl[e][m];
            float* op = out + (size_t)t * HID + n0 + tx * 4;
#pragma unroll
            for (int j = 0; j < 4; j++)
                atomicAdd(op + j, w * acc[i][j]);
        }
    }
}

// ---------------------------------------------------------------------------
// launch
// ---------------------------------------------------------------------------
extern "C" void kernel_launch(void* const* d_in, const int* in_sizes, int n_in,
                              void* d_out, int out_size) {
    const float* x  = (const float*)d_in[0];  // hidden_states [1,2048,1024]
    const float* wg = (const float*)d_in[1];  // [8,1024]
    const float* w1 = (const float*)d_in[2];  // [8,4096,1024]
    const float* w3 = (const float*)d_in[3];  // [8,4096,1024]
    const float* w2 = (const float*)d_in[4];  // [8,1024,4096]
    float* out = (float*)d_out;               // [2048*1024] f32

    k_zero_out<<<(out_size + 255) / 256, 256>>>(out, out_size);
    k_init<<<1, 32>>>();
    k_router<<<TOK, 128>>>(x, wg);
    // m-tiles fastest-varying for L2 reuse of weight tiles across the wave
    k_gemm1<<<dim3(TOK / 64, INTER / 64, NEXP), 256>>>(x, w1, w3);
    k_gemm2<<<dim3(TOK / 64, HID / 64, NEXP), 256>>>(w2, out);
}

// round 3
// speedup vs baseline: 6.5693x; 6.5693x over previous
#include <cuda_runtime.h>
#include <cuda_fp16.h>
#include <stdint.h>
#include <math.h>

#define TOK 2048
#define HID 1024
#define NEXP 8
#define INTER 4096
#define SOFTCAP 30.0f

// ---------------------------------------------------------------------------
// Device-global scratch (no allocation allowed anywhere)
// ---------------------------------------------------------------------------
__device__ int    g_cnt[NEXP];
__device__ int    g_list[NEXP][TOK];
__device__ int    g_tpair[TOK * 2];
__device__ float  g_tw[TOK * 2];

__device__ __half g_xh[TOK * HID];
__device__ __half g_w1h[(size_t)NEXP * INTER * HID];
__device__ __half g_w3h[(size_t)NEXP * INTER * HID];
__device__ __half g_w2h[(size_t)NEXP * HID * INTER];
__device__ float  g_h1[(size_t)NEXP * TOK * INTER];
__device__ float  g_h3[(size_t)NEXP * TOK * INTER];
__device__ __half g_acth[(size_t)NEXP * TOK * INTER];
__device__ float  g_pairout[(size_t)NEXP * TOK * HID];

// ---------------------------------------------------------------------------
// PTX helpers (baseline ISA only: sm_80-level, valid on plain sm_103 target)
// ---------------------------------------------------------------------------
__device__ __forceinline__ uint32_t smem_u32(const void* p) {
    uint32_t a;
    asm("{ .reg .u64 t; cvta.to.shared.u64 t, %1; cvt.u32.u64 %0, t; }"
        : "=r"(a) : "l"(p));
    return a;
}

__device__ __forceinline__ void cpasync16(uint32_t smem, const void* g) {
    asm volatile("cp.async.cg.shared.global [%0], [%1], 16;"
                 :: "r"(smem), "l"(g) : "memory");
}
#define CP_COMMIT() asm volatile("cp.async.commit_group;" ::: "memory")
#define CP_WAIT(n)  asm volatile("cp.async.wait_group %0;" :: "n"(n) : "memory")

__device__ __forceinline__ void ldsm4(uint32_t* r, uint32_t addr) {
    asm volatile("ldmatrix.sync.aligned.m8n8.x4.shared.b16 {%0,%1,%2,%3}, [%4];"
                 : "=r"(r[0]), "=r"(r[1]), "=r"(r[2]), "=r"(r[3]) : "r"(addr));
}

__device__ __forceinline__ void mma16816(float* d, const uint32_t* a,
                                         const uint32_t* b) {
    asm volatile(
        "mma.sync.aligned.m16n8k16.row.col.f32.f16.f16.f32 "
        "{%0,%1,%2,%3}, {%4,%5,%6,%7}, {%8,%9}, {%0,%1,%2,%3};"
        : "+f"(d[0]), "+f"(d[1]), "+f"(d[2]), "+f"(d[3])
        : "r"(a[0]), "r"(a[1]), "r"(a[2]), "r"(a[3]), "r"(b[0]), "r"(b[1]));
}

// ---------------------------------------------------------------------------
// fp32 -> fp16 conversion
// ---------------------------------------------------------------------------
__global__ void k_tohalf(const float4* __restrict__ in,
                         __half* __restrict__ out, int n4) {
    int i = blockIdx.x * blockDim.x + threadIdx.x;
    if (i >= n4) return;
    float4 v = in[i];
    __half2 h0 = __floats2half2_rn(v.x, v.y);
    __half2 h1 = __floats2half2_rn(v.z, v.w);
    uint2 u;
    u.x = *(uint32_t*)&h0;
    u.y = *(uint32_t*)&h1;
    *(uint2*)(out + (size_t)i * 4) = u;
}

__global__ void k_init() {
    if (threadIdx.x < NEXP) g_cnt[threadIdx.x] = 0;
}

// ---------------------------------------------------------------------------
// Router: logits -> softcap -> top2 -> renorm -> compact lists
// ---------------------------------------------------------------------------
__global__ void k_router(const float* __restrict__ x, const float* __restrict__ wg) {
    const int t = blockIdx.x;
    const float* xr = x + (size_t)t * HID;

    float acc[NEXP];
#pragma unroll
    for (int e = 0; e < NEXP; e++) acc[e] = 0.0f;

    for (int h = threadIdx.x; h < HID; h += 128) {
        float xv = xr[h];
#pragma unroll
        for (int e = 0; e < NEXP; e++)
            acc[e] = fmaf(xv, wg[e * HID + h], acc[e]);
    }
#pragma unroll
    for (int o = 16; o > 0; o >>= 1) {
#pragma unroll
        for (int e = 0; e < NEXP; e++)
            acc[e] += __shfl_down_sync(0xffffffffu, acc[e], o);
    }

    __shared__ float red[4][NEXP];
    int wid = threadIdx.x >> 5;
    int lane = threadIdx.x & 31;
    if (lane == 0) {
#pragma unroll
        for (int e = 0; e < NEXP; e++) red[wid][e] = acc[e];
    }
    __syncthreads();

    if (threadIdx.x == 0) {
        float l[NEXP];
#pragma unroll
        for (int e = 0; e < NEXP; e++) {
            float v = red[0][e] + red[1][e] + red[2][e] + red[3][e];
            l[e] = SOFTCAP * tanhf(v * (1.0f / SOFTCAP));
        }
        int i0 = 0;
#pragma unroll
        for (int e = 1; e < NEXP; e++)
            if (l[e] > l[i0]) i0 = e;
        int i1 = (i0 == 0) ? 1 : 0;
#pragma unroll
        for (int e = 0; e < NEXP; e++)
            if (e != i0 && l[e] > l[i1]) i1 = e;

        float m = l[i0];
        float e0 = expf(l[i0] - m);
        float e1 = expf(l[i1] - m);
        float inv = 1.0f / (e0 + e1);

        int p0 = atomicAdd(&g_cnt[i0], 1);
        g_list[i0][p0] = t;
        int p1 = atomicAdd(&g_cnt[i1], 1);
        g_list[i1][p1] = t;

        g_tpair[t * 2 + 0] = i0 * TOK + p0;
        g_tpair[t * 2 + 1] = i1 * TOK + p1;
        g_tw[t * 2 + 0] = e0 * inv;
        g_tw[t * 2 + 1] = e1 * inv;
    }
}

// ---------------------------------------------------------------------------
// Grouped GEMM: C[e][m][n] = rowsA(m) . B[e][n][:]  (fp16 in, f32 out)
// CTA tile 128x128, K-chunk 64, 2-stage cp.async pipeline, mma.sync 16x8x16
// grid = (TOK/128, Nt/128, NEXP), 256 threads (8 warps, 2m x 4n of 64x32)
// ---------------------------------------------------------------------------
#define MM_SMEM (1024 + 4 * 16384)

__global__ void __launch_bounds__(256) k_mm(const __half* __restrict__ A,
                                            const __half* __restrict__ B,
                                            float* __restrict__ C,
                                            int K, int Nt, int gather) {
    extern __shared__ char smem[];
    const uint32_t sb = smem_u32(smem);
    int* rows_s = (int*)smem;

    const int e = blockIdx.z;
    const int cnt = g_cnt[e];
    const int m0 = blockIdx.x * 128;
    if (m0 >= cnt) return;
    const int n0 = blockIdx.y * 128;

    const int tid = threadIdx.x;
    if (tid < 128) {
        int m = m0 + tid;
        int ridx = m < cnt ? m : cnt - 1;
        rows_s[tid] = gather ? g_list[e][ridx] : (e * TOK + ridx);
    }
    __syncthreads();

    // smem tile bases: A buf0/1, B buf0/1 (16KB each), after 1KB header
    const uint32_t sA0 = sb + 1024;
    const uint32_t sB0 = sb + 1024 + 32768;

    // per-thread load slots (4 x 16B for A, 4 for B per chunk)
    size_t arow[4], brow[4];
    uint32_t soff[4];
#pragma unroll
    for (int i = 0; i < 4; i++) {
        int lin = tid + 256 * i;
        int r = lin >> 3;
        int kc = lin & 7;
        soff[i] = ((uint32_t)r << 7) | (((uint32_t)kc << 4) ^ (((uint32_t)(r & 7)) << 4));
        arow[i] = (size_t)rows_s[r] * K + kc * 8;
        brow[i] = ((size_t)e * Nt + n0 + r) * K + kc * 8;
    }

    const int lane = tid & 31;
    const int w = tid >> 5;
    const int mw = (w >> 2) * 64;   // 0 or 64
    const int nw = (w & 3) * 32;    // 0,32,64,96

    float acc[4][4][4];
#pragma unroll
    for (int mi = 0; mi < 4; mi++)
#pragma unroll
        for (int nj = 0; nj < 4; nj++)
#pragma unroll
            for (int q = 0; q < 4; q++) acc[mi][nj][q] = 0.0f;

    const int nch = K >> 6;

    // prefetch chunk 0
    {
#pragma unroll
        for (int i = 0; i < 4; i++)
            cpasync16(sA0 + soff[i], A + arow[i]);
#pragma unroll
        for (int i = 0; i < 4; i++)
            cpasync16(sB0 + soff[i], B + brow[i]);
        CP_COMMIT();
    }

    for (int it = 0; it < nch; it++) {
        if (it + 1 < nch) {
            const int k0 = (it + 1) << 6;
            const uint32_t boff = ((it + 1) & 1) ? 16384u : 0u;
#pragma unroll
            for (int i = 0; i < 4; i++)
                cpasync16(sA0 + boff + soff[i], A + arow[i] + k0);
#pragma unroll
            for (int i = 0; i < 4; i++)
                cpasync16(sB0 + boff + soff[i], B + brow[i] + k0);
            CP_COMMIT();
            CP_WAIT(1);
        } else {
            CP_WAIT(0);
        }
        __syncthreads();

        const uint32_t aB = sA0 + ((it & 1) ? 16384u : 0u);
        const uint32_t bB = sB0 + ((it & 1) ? 16384u : 0u);

#pragma unroll
        for (int kk = 0; kk < 4; kk++) {
            uint32_t af[4][4];
#pragma unroll
            for (int mi = 0; mi < 4; mi++) {
                int mat = lane >> 3;
                int row = mw + mi * 16 + (lane & 7) + (mat & 1) * 8;
                int kb = kk * 32 + (mat >> 1) * 16;
                uint32_t so = ((uint32_t)row << 7) |
                              ((uint32_t)kb ^ (((uint32_t)(row & 7)) << 4));
                ldsm4(af[mi], aB + so);
            }
            uint32_t bf[4][2];
#pragma unroll
            for (int nb = 0; nb < 2; nb++) {
                int mat = lane >> 3;
                int row = nw + nb * 16 + (mat >> 1) * 8 + (lane & 7);
                int kb = kk * 32 + (mat & 1) * 16;
                uint32_t so = ((uint32_t)row << 7) |
                              ((uint32_t)kb ^ (((uint32_t)(row & 7)) << 4));
                uint32_t r4[4];
                ldsm4(r4, bB + so);
                bf[nb * 2 + 0][0] = r4[0];
                bf[nb * 2 + 0][1] = r4[1];
                bf[nb * 2 + 1][0] = r4[2];
                bf[nb * 2 + 1][1] = r4[3];
            }
#pragma unroll
            for (int mi = 0; mi < 4; mi++)
#pragma unroll
                for (int nj = 0; nj < 4; nj++)
                    mma16816(acc[mi][nj], af[mi], bf[nj]);
        }
        __syncthreads();
    }

    // epilogue
#pragma unroll
    for (int mi = 0; mi < 4; mi++) {
        int m1 = m0 + mw + mi * 16 + (lane >> 2);
#pragma unroll
        for (int nj = 0; nj < 4; nj++) {
            int n = n0 + nw + nj * 8 + (lane & 3) * 2;
            float* cp = C + ((size_t)e * TOK + m1) * Nt + n;
            if (m1 < cnt) {
                float2 v0 = make_float2(acc[mi][nj][0], acc[mi][nj][1]);
                *(float2*)cp = v0;
            }
            if (m1 + 8 < cnt) {
                float2 v1 = make_float2(acc[mi][nj][2], acc[mi][nj][3]);
                *(float2*)(cp + (size_t)8 * Nt) = v1;
            }
        }
    }
}

// ---------------------------------------------------------------------------
// act = gelu(h1) * h3 -> fp16 (only live rows)
// ---------------------------------------------------------------------------
__global__ void k_actfuse() {
    size_t i = (size_t)blockIdx.x * 256 + threadIdx.x;  // float4 index
    int row = (int)(i >> 10);                           // INTER/4 = 1024
    int e = row >> 11;                                  // TOK = 2048 rows/exp
    int m = row & (TOK - 1);
    if (m >= g_cnt[e]) return;
    float4 a = *((const float4*)g_h1 + i);
    float4 b = *((const float4*)g_h3 + i);
    float v0 = 0.5f * a.x * (1.0f + erff(a.x * 0.70710678118654752f)) * b.x;
    float v1 = 0.5f * a.y * (1.0f + erff(a.y * 0.70710678118654752f)) * b.y;
    float v2 = 0.5f * a.z * (1.0f + erff(a.z * 0.70710678118654752f)) * b.z;
    float v3 = 0.5f * a.w * (1.0f + erff(a.w * 0.70710678118654752f)) * b.w;
    __half2 h0 = __floats2half2_rn(v0, v1);
    __half2 h1 = __floats2half2_rn(v2, v3);
    uint2 u;
    u.x = *(uint32_t*)&h0;
    u.y = *(uint32_t*)&h1;
    *(uint2*)(g_acth + i * 4) = u;
}

// ---------------------------------------------------------------------------
// out[t] = w0 * pairout[p0] + w1 * pairout[p1]
// ---------------------------------------------------------------------------
__global__ void k_combine(float* __restrict__ out) {
    int i = blockIdx.x * 256 + threadIdx.x;
    int t = i >> 10;
    int h = i & (HID - 1);
    out[i] = g_tw[t * 2 + 0] * g_pairout[(size_t)g_tpair[t * 2 + 0] * HID + h] +
             g_tw[t * 2 + 1] * g_pairout[(size_t)g_tpair[t * 2 + 1] * HID + h];
}

// ---------------------------------------------------------------------------
// launch
// ---------------------------------------------------------------------------
extern "C" void kernel_launch(void* const* d_in, const int* in_sizes, int n_in,
                              void* d_out, int out_size) {
    const float* x  = (const float*)d_in[0];
    const float* wg = (const float*)d_in[1];
    const float* w1 = (const float*)d_in[2];
    const float* w3 = (const float*)d_in[3];
    const float* w2 = (const float*)d_in[4];
    float* out = (float*)d_out;

    cudaFuncSetAttribute(k_mm, cudaFuncAttributeMaxDynamicSharedMemorySize, MM_SMEM);

    __half *xh, *w1h, *w3h, *w2h;
    float *h1, *h3, *po;
    __half *acth;
    cudaGetSymbolAddress((void**)&xh, g_xh);
    cudaGetSymbolAddress((void**)&w1h, g_w1h);
    cudaGetSymbolAddress((void**)&w3h, g_w3h);
    cudaGetSymbolAddress((void**)&w2h, g_w2h);
    cudaGetSymbolAddress((void**)&h1, g_h1);
    cudaGetSymbolAddress((void**)&h3, g_h3);
    cudaGetSymbolAddress((void**)&acth, g_acth);
    cudaGetSymbolAddress((void**)&po, g_pairout);

    const int nw4 = (int)((size_t)NEXP * INTER * HID / 4);  // 8388608
    k_tohalf<<<(TOK * HID / 4 + 255) / 256, 256>>>((const float4*)x, xh, TOK * HID / 4);
    k_tohalf<<<(nw4 + 255) / 256, 256>>>((const float4*)w1, w1h, nw4);
    k_tohalf<<<(nw4 + 255) / 256, 256>>>((const float4*)w3, w3h, nw4);
    k_tohalf<<<(nw4 + 255) / 256, 256>>>((const float4*)w2, w2h, nw4);

    k_init<<<1, 32>>>();
    k_router<<<TOK, 128>>>(x, wg);

    k_mm<<<dim3(TOK / 128, INTER / 128, NEXP), 256, MM_SMEM>>>(xh, w1h, h1, HID, INTER, 1);
    k_mm<<<dim3(TOK / 128, INTER / 128, NEXP), 256, MM_SMEM>>>(xh, w3h, h3, HID, INTER, 1);
    k_actfuse<<<(int)((size_t)NEXP * TOK * INTER / 4 / 256), 256>>>();
    k_mm<<<dim3(TOK / 128, HID / 128, NEXP), 256, MM_SMEM>>>(acth, w2h, po, INTER, HID, 0);
    k_combine<<<TOK * HID / 256, 256>>>(out);
}